// round 2
// baseline (speedup 1.0000x reference)
#include <cuda_runtime.h>
#include <cstdint>

// Embedding gather: out[i, :] = table[indices[i], :]
// indices: int32[4194304] (JAX silently downcasts int64 -> int32 without x64),
// table: float32[1000000, 16], out: float32[4194304, 16]
//
// Each thread handles one float4 (16 B). 4 consecutive threads share a row:
// their index loads hit the same cacheline; their table loads form one
// contiguous 64 B transaction. Output stores are perfectly coalesced and use
// streaming (.cs) so the 256 MB output stream does not evict the 64 MB table
// from L2 (the table fits in B300's ~126 MB L2).

static constexpr int EMBED_F4 = 4;   // 16 floats = 4 x float4 per row

__global__ void __launch_bounds__(256) gather_kernel(
    const int* __restrict__ indices,
    const float4* __restrict__ table4,
    float4* __restrict__ out4,
    int num_indices)
{
    int j = blockIdx.x * blockDim.x + threadIdx.x;   // float4 element id
    int total = num_indices * EMBED_F4;
    if (j >= total) return;

    int row = j >> 2;          // which output row
    int sub = j & 3;           // which float4 within the row

    long long idx = (long long)__ldg(&indices[row]);
    float4 v = __ldg(&table4[idx * EMBED_F4 + sub]);

    // streaming store: evict-first, keep table resident in L2
    __stcs(&out4[j], v);
}

extern "C" void kernel_launch(void* const* d_in, const int* in_sizes, int n_in,
                              void* d_out, int out_size)
{
    // Resolve input order by size: indices has 4,194,304 elements,
    // table has 16,000,000 (1,000,000 x 16) elements.
    int idx_slot = 0, tab_slot = 1;
    if (n_in >= 2 && in_sizes[0] > in_sizes[1]) { idx_slot = 1; tab_slot = 0; }

    const int*    indices = (const int*)d_in[idx_slot];
    const float4* table4  = (const float4*)d_in[tab_slot];
    float4*       out4    = (float4*)d_out;

    int num_indices = in_sizes[idx_slot];
    int total_f4 = num_indices * EMBED_F4;   // 16,777,216

    int threads = 256;
    int blocks = (total_f4 + threads - 1) / threads;
    gather_kernel<<<blocks, threads>>>(indices, table4, out4, num_indices);
}

// round 4
// speedup vs baseline: 1.2910x; 1.2910x over previous
#include <cuda_runtime.h>
#include <cstdint>

// Embedding gather: out[i, :] = table[indices[i], :]
// indices: int32[4194304], table: float32[1000000, 16], out: float32[4194304, 16]
//
// R2 measured 410 MB DRAM traffic vs 336 MB compulsory (table re-fetched ~74MB).
// Fix: L2 eviction-priority via createpolicy + ld.global.nc.L2::cache_hint
// (direct .L2::evict_* ld qualifiers are restricted to .v8 on sm_103 per ptxas).
//   - table loads:  evict_last policy  -> table (64 MB) stays in L2 (126 MB)
//   - index loads:  __ldcs (streaming) -> read-once, don't pollute
//   - out stores:   __stcs (streaming) -> write-once, don't pollute
//
// Table gather uses 256-bit loads: 2 threads per row, 32 B each -> one 64 B
// contiguous transaction per row; output stores are two coalesced 32 B stores.

struct __align__(32) f8 { float4 a, b; };

__device__ __forceinline__ f8 ldg_table_evict_last(const f8* p, uint64_t policy) {
    f8 v;
    asm volatile(
        "ld.global.nc.L2::cache_hint.v8.f32 {%0,%1,%2,%3,%4,%5,%6,%7}, [%8], %9;"
        : "=f"(v.a.x), "=f"(v.a.y), "=f"(v.a.z), "=f"(v.a.w),
          "=f"(v.b.x), "=f"(v.b.y), "=f"(v.b.z), "=f"(v.b.w)
        : "l"(p), "l"(policy));
    return v;
}

static constexpr int ROW_HALVES = 2;   // 16 floats = 2 x 32 B halves per row

__global__ void __launch_bounds__(256) gather_kernel(
    const int* __restrict__ indices,
    const f8* __restrict__ table8,     // table as 32 B chunks: 2 per row
    float4* __restrict__ out4,
    int num_indices)
{
    uint64_t policy;
    asm volatile("createpolicy.fractional.L2::evict_last.b64 %0, 1.0;" : "=l"(policy));

    int j = blockIdx.x * blockDim.x + threadIdx.x;   // 32 B chunk id
    int total = num_indices * ROW_HALVES;
    if (j >= total) return;

    int row = j >> 1;          // output row
    int sub = j & 1;           // which 32 B half of the row

    long long idx = (long long)__ldcs(&indices[row]);
    f8 v = ldg_table_evict_last(&table8[idx * ROW_HALVES + sub], policy);

    // streaming stores: evict-first, keep table resident in L2
    __stcs(&out4[j * 2 + 0], v.a);
    __stcs(&out4[j * 2 + 1], v.b);
}

extern "C" void kernel_launch(void* const* d_in, const int* in_sizes, int n_in,
                              void* d_out, int out_size)
{
    // Resolve input order by size: indices = 4,194,304 elems, table = 16,000,000.
    int idx_slot = 0, tab_slot = 1;
    if (n_in >= 2 && in_sizes[0] > in_sizes[1]) { idx_slot = 1; tab_slot = 0; }

    const int* indices = (const int*)d_in[idx_slot];
    const f8*  table8  = (const f8*)d_in[tab_slot];
    float4*    out4    = (float4*)d_out;

    int num_indices = in_sizes[idx_slot];
    int total_chunks = num_indices * ROW_HALVES;   // 8,388,608

    int threads = 256;
    int blocks = (total_chunks + threads - 1) / threads;
    gather_kernel<<<blocks, threads>>>(indices, table8, out4, num_indices);
}